// round 13
// baseline (speedup 1.0000x reference)
#include <cuda_runtime.h>
#include <cuda_bf16.h>
#include <math.h>
#include <stdint.h>

#define SRCL  50
#define NB    128
#define TRGV  30000
#define NPV   30080
#define NCB   235
#define DST   39
#define GROWS 4992

// ----------------------------- device scratch -------------------------------
__device__ __align__(16) float          g_xin[2*SRCL*NB*256];
__device__ __align__(16) float          g_encout[SRCL*NB*128];
__device__ __align__(16) float          g_h0[NB*128];
__device__ __align__(16) float          g_c0[NB*128];
__device__ __align__(16) float          g_dpre[DST*NB*512];
__device__ __align__(16) __nv_bfloat16  g_hall[GROWS*128];
__device__ __align__(16) __nv_bfloat16  g_genW[NPV*128];
__device__ __align__(16) float          g_genb[NPV];
__device__ __align__(16) unsigned       g_Wip[64*128];     // attn_Wi  [k2][d]
__device__ __align__(16) unsigned       g_Wop[128*128];    // attn_Wo  [k2][j]
__device__ __align__(16) unsigned       g_whhp[64*512];    // dec_w_hh [k2][j]
__device__ __align__(16) unsigned       g_wihAp[64*512];   // dec_w_ih[:, :128] [k2][j]
__device__ __align__(16) unsigned       g_ewhh[2*32*256];  // enc_w_hh packed [dir][k2][j]
__device__ __align__(16) float          g_part[NCB*GROWS];
__device__ __align__(16) float          g_lse[GROWS];
__device__ __align__(16) __nv_bfloat16  g_logit[(size_t)GROWS*NPV];   // 300 MB bf16 logits

// ----------------------------- helpers --------------------------------------
__device__ __forceinline__ unsigned pk2(float a, float b){
    __nv_bfloat162 h = __floats2bfloat162_rn(a, b);
    return *reinterpret_cast<unsigned*>(&h);
}
__device__ __forceinline__ float2 up2(unsigned u){
    __nv_bfloat162 h = *reinterpret_cast<__nv_bfloat162*>(&u);
    return __bfloat1622float2(h);
}
__device__ __forceinline__ float sigf(float x){
    return __fdividef(1.f, 1.f + __expf(-x));
}
__device__ __forceinline__ float tanh_(float x){
    float xc = fminf(15.f, fmaxf(-15.f, x));
    float e  = __expf(2.f*xc);
    return __fdividef(e - 1.f, e + 1.f);
}
__device__ __forceinline__ void mma16816(float* d, const unsigned* a, const unsigned* b){
    asm volatile("mma.sync.aligned.m16n8k16.row.col.f32.bf16.bf16.f32 "
        "{%0,%1,%2,%3}, {%4,%5,%6,%7}, {%8,%9}, {%0,%1,%2,%3};"
        : "+f"(d[0]), "+f"(d[1]), "+f"(d[2]), "+f"(d[3])
        : "r"(a[0]), "r"(a[1]), "r"(a[2]), "r"(a[3]), "r"(b[0]), "r"(b[1]));
}
__device__ __forceinline__ void ldsm4(unsigned* r, uint32_t addr){
    asm volatile("ldmatrix.sync.aligned.m8n8.x4.shared.b16 {%0,%1,%2,%3}, [%4];"
        : "=r"(r[0]), "=r"(r[1]), "=r"(r[2]), "=r"(r[3]) : "r"(addr));
}
__device__ __forceinline__ uint32_t s2u(const void* p){
    uint32_t a;
    asm("{ .reg .u64 t; cvta.to.shared.u64 t, %1; cvt.u32.u64 %0, t; }" : "=r"(a) : "l"(p));
    return a;
}

// ---------------- prep A: weight packing ------------------------------------
__global__ void __launch_bounds__(256) k_pack(
    const float* __restrict__ ewhf, const float* __restrict__ ewhb,
    const float* __restrict__ Wi,   const float* __restrict__ Wo,
    const float* __restrict__ dwih, const float* __restrict__ dwhh,
    const float* __restrict__ genW, const float* __restrict__ genb)
{
    int blk = blockIdx.x, tid = threadIdx.x;
    if(blk < 416){                                   // ---- pack small weights
        int idx = blk*256 + tid;
        if(idx < 8192){ int k2=idx>>7, d=idx&127;
            g_Wip[idx] = pk2(Wi[d*128+2*k2], Wi[d*128+2*k2+1]); return; }
        idx -= 8192;
        if(idx < 16384){ int k2=idx>>7, j=idx&127;
            g_Wop[idx] = pk2(Wo[j*256+2*k2], Wo[j*256+2*k2+1]); return; }
        idx -= 16384;
        if(idx < 32768){ int k2=idx>>9, j=idx&511;
            g_whhp[idx] = pk2(dwhh[j*128+2*k2], dwhh[j*128+2*k2+1]); return; }
        idx -= 32768;
        if(idx < 32768){ int k2=idx>>9, j=idx&511;
            g_wihAp[idx] = pk2(dwih[j*158+2*k2], dwih[j*158+2*k2+1]); return; }
        idx -= 32768;
        if(idx < 16384){ int dir=idx>>13, r=idx&8191, k2=r>>8, j=r&255;
            const float* w = dir ? ewhb : ewhf;
            g_ewhh[dir*8192 + k2*256 + j] = pk2(w[j*64+2*k2], w[j*64+2*k2+1]); }
        return;
    }
    blk -= 416;
    {                                                // ---- pack generator
        int idx = blk*256 + tid;                     // < NPV*128
        int n = idx>>7, k = idx&127;
        g_genW[idx] = __float2bfloat16(n < TRGV ? genW[n*128+k] : 0.f);
        if(idx < NPV) g_genb[idx] = (idx < TRGV) ? genb[idx] : -1e30f;
        return;
    }
}

// ---------------- prep B: embedding pre-gates --------------------------------
__global__ void __launch_bounds__(256) k_pemb(
    const int* __restrict__ src, const int* __restrict__ trg,
    const float* __restrict__ EEMB, const float* __restrict__ DEMB,
    const float* __restrict__ ewf,  const float* __restrict__ ebf,
    const float* __restrict__ ewb,  const float* __restrict__ ebb,
    const float* __restrict__ dwih, const float* __restrict__ db)
{
    __shared__ float emb[16][32];
    int blk = blockIdx.x, tid = threadIdx.x;
    if(blk < 800){                                   // ---- encoder input gates
        int bi = blk>>3, b0 = (blk&7)*16;
        int dir = bi / SRCL, s = bi % SRCL;
        int j = tid;
        const float* w = dir ? ewb : ewf;
        float wr[30];
        #pragma unroll
        for(int e=0;e<30;e++) wr[e] = w[j*30+e];
        float bj = (dir ? ebb : ebf)[j];
        for(int i=tid;i<480;i+=256){
            int q=i/30, e=i%30; int tok = src[s*NB + b0 + q];
            emb[q][e] = EEMB[tok*30+e];
        }
        __syncthreads();
        #pragma unroll 4
        for(int q=0;q<16;q++){
            float a = bj;
            #pragma unroll
            for(int e=0;e<30;e++) a += wr[e]*emb[q][e];
            g_xin[((dir*SRCL+s)*NB + b0 + q)*256 + j] = a;
        }
        return;
    }
    blk -= 800;
    {                                                // ---- decoder pre-gates
        int t = blk>>4, sub = blk&15;
        int b0 = (sub>>1)*16;
        int j  = (sub&1)*256 + tid;
        float wr[30];
        #pragma unroll
        for(int e=0;e<30;e++) wr[e] = dwih[j*158 + 128 + e];
        float bj = db[j];
        for(int i=tid;i<480;i+=256){
            int q=i/30, e=i%30; int tok = trg[t*NB + b0 + q];
            emb[q][e] = DEMB[tok*30+e];
        }
        __syncthreads();
        #pragma unroll 4
        for(int q=0;q<16;q++){
            float a = bj;
            #pragma unroll
            for(int e=0;e<30;e++) a += wr[e]*emb[q][e];
            g_dpre[(t*NB + b0 + q)*512 + j] = a;
        }
        return;
    }
}

// ------------------------------- encoder recurrence --------------------------
__global__ void k_enc()
{
    extern __shared__ char sm[];
    unsigned* ws = (unsigned*)sm;                       // 16384 u (64KB)
    float* hs = (float*)(sm + 65536);                   // 128
    float* cs = hs + 128;                               // 128
    float* gb = cs + 128;                               // 512
    int b = blockIdx.x, tid = threadIdx.x;

    { uint4* d4=(uint4*)ws; const uint4* s4=(const uint4*)g_ewhh;
      for(int i=tid;i<4096;i+=256) d4[i]=s4[i]; }
    if(tid < 128){ hs[tid]=0.f; cs[tid]=0.f; }
    __syncthreads();

    for(int t=0;t<SRCL;t++){
        float af = g_xin[((0*SRCL + t        )*NB+b)*256 + tid];
        float ab = g_xin[((1*SRCL + (SRCL-1-t))*NB+b)*256 + tid];
        #pragma unroll 8
        for(int k2=0;k2<32;k2++){
            float h0 = hs[2*k2], h1 = hs[2*k2+1];
            float2 wf2 = up2(ws[k2*256 + tid]);
            af += h0*wf2.x + h1*wf2.y;
            float g0 = hs[64+2*k2], g1 = hs[64+2*k2+1];
            float2 wb2 = up2(ws[8192 + k2*256 + tid]);
            ab += g0*wb2.x + g1*wb2.y;
        }
        gb[tid] = af; gb[256+tid] = ab;
        __syncthreads();
        if(tid < 128){
            int dir = tid>>6, d = tid&63;
            float* g = gb + dir*256;
            float iv=g[d], fv=g[64+d], gv=g[128+d], ov=g[192+d];
            float cn = sigf(fv)*cs[dir*64+d] + sigf(iv)*tanh_(gv);
            float hn = sigf(ov)*tanh_(cn);
            cs[dir*64+d]=cn; hs[dir*64+d]=hn;
            int s_out = dir ? (SRCL-1-t) : t;
            g_encout[(s_out*NB+b)*128 + dir*64 + d] = hn;
        }
        __syncthreads();
    }
    if(tid < 64){
        g_h0[b*128+2*tid]   = hs[tid];
        g_h0[b*128+2*tid+1] = hs[64+tid];
        g_c0[b*128+2*tid]   = cs[tid];
        g_c0[b*128+2*tid+1] = cs[64+tid];
    }
}

// ------------------------------- decoder recurrence --------------------------
__global__ void k_dec()
{
    extern __shared__ char sm[];
    unsigned* whh  = (unsigned*)sm;                 // 32768 u  @0
    unsigned* wop  = (unsigned*)(sm + 131072);      // 16384 u
    float*    encs = (float*)  (sm + 196608);       // 6400 f
    float*    h    = (float*)  (sm + 222208);       // 128
    float*    c    = h   + 128;
    float*    semi = c   + 128;
    float*    st   = semi+ 128;
    float*    ct   = st  + 128;
    float*    es   = ct  + 128;                     // 64
    float*    sc   = es  + 64;                      // 64
    float*    gb   = sc  + 64;                      // 512
    int b = blockIdx.x, tid = threadIdx.x;
    int lane = tid & 31, w = tid >> 5;

    { uint4* d4=(uint4*)whh; const uint4* s4=(const uint4*)g_whhp;
      for(int i=tid;i<8192;i+=256) d4[i]=s4[i]; }
    { uint4* d4=(uint4*)wop; const uint4* s4=(const uint4*)g_Wop;
      for(int i=tid;i<4096;i+=256) d4[i]=s4[i]; }
    { float4* d4=(float4*)encs; const float4* s4=(const float4*)g_encout;
      for(int i=tid;i<1600;i+=256){ int s=i>>5, r=i&31; d4[i]=s4[(s*NB+b)*32 + r]; } }
    if(tid < 128){ h[tid]=g_h0[b*128+tid]; c[tid]=g_c0[b*128+tid]; }
    __syncthreads();

    for(int t=0;t<DST;t++){
        if(tid < 128){
            float a = 0.f;
            #pragma unroll 8
            for(int k2=0;k2<64;k2++){
                float2 w2 = up2(__ldg(&g_Wip[k2*128 + tid]));
                a += h[2*k2]*w2.x + h[2*k2+1]*w2.y;
            }
            semi[tid] = a;
        }
        __syncthreads();
        for(int s=w; s<SRCL; s+=8){
            const float* er = encs + s*128;
            float a = er[lane]*semi[lane] + er[lane+32]*semi[lane+32]
                    + er[lane+64]*semi[lane+64] + er[lane+96]*semi[lane+96];
            #pragma unroll
            for(int o=16;o>0;o>>=1) a += __shfl_xor_sync(0xffffffffu, a, o);
            if(lane==0) es[s] = a;
        }
        __syncthreads();
        if(w == 0){
            float v0 = (lane    < SRCL) ? es[lane]    : -1e30f;
            float v1 = (lane+32 < SRCL) ? es[lane+32] : -1e30f;
            float m = fmaxf(v0, v1);
            #pragma unroll
            for(int o=16;o>0;o>>=1) m = fmaxf(m, __shfl_xor_sync(0xffffffffu, m, o));
            float e0 = (lane    < SRCL) ? __expf(v0-m) : 0.f;
            float e1 = (lane+32 < SRCL) ? __expf(v1-m) : 0.f;
            float ssum = e0 + e1;
            #pragma unroll
            for(int o=16;o>0;o>>=1) ssum += __shfl_xor_sync(0xffffffffu, ssum, o);
            float inv = __fdividef(1.f, ssum);
            if(lane    < SRCL) sc[lane]    = e0*inv;
            if(lane+32 < SRCL) sc[lane+32] = e1*inv;
        }
        __syncthreads();
        if(tid < 128){
            float a = 0.f;
            #pragma unroll 10
            for(int s=0;s<SRCL;s++) a += sc[s]*encs[s*128 + tid];
            st[tid] = a;
        }
        __syncthreads();
        if(tid < 128){
            float a = 0.f;
            #pragma unroll 8
            for(int k2=0;k2<64;k2++){
                float2 w2 = up2(wop[k2*128 + tid]);
                a += st[2*k2]*w2.x + st[2*k2+1]*w2.y;
            }
            #pragma unroll 8
            for(int k2=0;k2<64;k2++){
                float2 w2 = up2(wop[(64+k2)*128 + tid]);
                a += h[2*k2]*w2.x + h[2*k2+1]*w2.y;
            }
            ct[tid] = tanh_(a);
        }
        __syncthreads();
        {
            const float* pre = g_dpre + (t*NB+b)*512;
            float a0 = __ldg(&pre[tid]);
            float a1 = __ldg(&pre[tid+256]);
            #pragma unroll 4
            for(int k2=0;k2<64;k2++){
                float x0 = ct[2*k2], x1 = ct[2*k2+1];
                float2 wA0 = up2(__ldg(&g_wihAp[k2*512 + tid]));
                float2 wA1 = up2(__ldg(&g_wihAp[k2*512 + tid + 256]));
                a0 += x0*wA0.x + x1*wA0.y;
                a1 += x0*wA1.x + x1*wA1.y;
                float y0 = h[2*k2], y1 = h[2*k2+1];
                float2 wH0 = up2(whh[k2*512 + tid]);
                float2 wH1 = up2(whh[k2*512 + tid + 256]);
                a0 += y0*wH0.x + y1*wH0.y;
                a1 += y0*wH1.x + y1*wH1.y;
            }
            gb[tid] = a0; gb[tid+256] = a1;
        }
        __syncthreads();
        if(tid < 128){
            float iv=gb[tid], fv=gb[128+tid], gv=gb[256+tid], ov=gb[384+tid];
            float cn = sigf(fv)*c[tid] + sigf(iv)*tanh_(gv);
            float hn = sigf(ov)*tanh_(cn);
            c[tid]=cn; h[tid]=hn;
            g_hall[(t*NB+b)*128 + tid] = __float2bfloat16(hn);
        }
        __syncthreads();
    }
}

// ------------------- generator GEMM (mma.sync + ldmatrix) --------------------
// CTA: 128(M) x 128(N), K=128 resident. Logits stored bf16 to g_logit.
#define GP 136
#define CP 132
__global__ void __launch_bounds__(256) k_gen()
{
    extern __shared__ char sm[];
    __nv_bfloat16* As = (__nv_bfloat16*)sm;
    __nv_bfloat16* Bs = As + 128*GP;
    int tid = threadIdx.x, w = tid>>5, lane = tid&31;
    int mb = blockIdx.y, nb = blockIdx.x;

    const uint4* Asrc = (const uint4*)(g_hall + (size_t)mb*128*128);
    const uint4* Bsrc = (const uint4*)(g_genW + (size_t)nb*128*128);
    for(int i=tid;i<2048;i+=256){
        int r=i>>4, c=i&15;
        *(uint4*)(As + r*GP + c*8) = Asrc[i];
    }
    for(int i=tid;i<2048;i+=256){
        int r=i>>4, c=i&15;
        *(uint4*)(Bs + r*GP + c*8) = Bsrc[i];
    }
    __syncthreads();

    int wm = w & 3, wn = w >> 2;                    // warp grid 4x2
    int m0 = wm*32, n0 = wn*64;

    float acc[2][8][4];
    #pragma unroll
    for(int mi=0;mi<2;mi++)
        #pragma unroll
        for(int ni=0;ni<8;ni++)
            #pragma unroll
            for(int q=0;q<4;q++) acc[mi][ni][q] = 0.f;

    // ldmatrix lane->row/khalf mapping (byte addresses, pitch 2*GP = 272B)
    uint32_t As_u = s2u(As), Bs_u = s2u(Bs);
    // A x4: row = m0+mi*16+(lane&15), khalf = lane>>4
    uint32_t aAddr = As_u + (uint32_t)((m0 + (lane & 15))*GP + (lane >> 4)*8)*2;
    // B x4 (2 ni tiles): row = n0+nip*16+8*((lane>>4)&1)+(lane&7), khalf=(lane>>3)&1
    uint32_t bAddr = Bs_u + (uint32_t)((n0 + ((lane >> 4) & 1)*8 + (lane & 7))*GP
                                       + ((lane >> 3) & 1)*8)*2;

    #pragma unroll
    for(int ks=0;ks<8;ks++){
        uint32_t kOff = ks*32;                       // 16 bf16 = 32 bytes
        unsigned a[2][4];
        ldsm4(a[0], aAddr + kOff);
        ldsm4(a[1], aAddr + 16*GP*2 + kOff);
        #pragma unroll
        for(int nip=0;nip<4;nip++){
            unsigned bq[4];
            ldsm4(bq, bAddr + (uint32_t)(nip*16*GP)*2 + kOff);
            mma16816(acc[0][nip*2+0], a[0], bq+0);
            mma16816(acc[1][nip*2+0], a[1], bq+0);
            mma16816(acc[0][nip*2+1], a[0], bq+2);
            mma16816(acc[1][nip*2+1], a[1], bq+2);
        }
    }
    __syncthreads();                                 // before smem reuse as C

    int lq = lane>>2, lr = lane&3;
    float* Cs = (float*)sm;
    #pragma unroll
    for(int mi=0;mi<2;mi++){
        #pragma unroll
        for(int ni=0;ni<8;ni++){
            float* cr = Cs + (m0+mi*16+lq)*CP + n0 + ni*8 + 2*lr;
            cr[0] = acc[mi][ni][0]; cr[1] = acc[mi][ni][1];
            cr[8*CP] = acc[mi][ni][2]; cr[8*CP+1] = acc[mi][ni][3];
        }
    }
    __syncthreads();

    // epilogue: warp per row, lane covers 4 cols; bf16 logits + f32 exp sums
    float4 bias = *(const float4*)(g_genb + nb*128 + lane*4);
    __nv_bfloat16* lbase = g_logit + (size_t)(mb*128)*NPV + nb*128 + lane*4;
    #pragma unroll 4
    for(int rr=0; rr<16; rr++){
        int r = w*16 + rr;
        const float* row = Cs + r*CP + lane*4;
        float v0 = row[0] + bias.x;
        float v1 = row[1] + bias.y;
        float v2 = row[2] + bias.z;
        float v3 = row[3] + bias.w;
        float s = __expf(v0) + __expf(v1) + __expf(v2) + __expf(v3);
        #pragma unroll
        for(int o=16;o>0;o>>=1) s += __shfl_xor_sync(0xffffffffu, s, o);
        if(lane == 0) g_part[nb*GROWS + mb*128 + r] = s;
        __nv_bfloat162 p0 = __floats2bfloat162_rn(v0, v1);
        __nv_bfloat162 p1 = __floats2bfloat162_rn(v2, v3);
        uint2 pk;
        pk.x = *reinterpret_cast<unsigned*>(&p0);
        pk.y = *reinterpret_cast<unsigned*>(&p1);
        *(uint2*)(lbase + (size_t)r*NPV) = pk;
    }
}

__global__ void k_lse()
{
    int m = blockIdx.x*256 + threadIdx.x;
    if(m >= GROWS) return;
    float s = 0.f;
    for(int nb=0;nb<NCB;nb++) s += g_part[nb*GROWS + m];
    g_lse[m] = logf(s);
}

// rows < NB: constant row0; rows >= NB: out = bf16logit - lse (streaming)
__global__ void __launch_bounds__(256) k_fixrow(float* __restrict__ out)
{
    int c8 = blockIdx.x*256 + threadIdx.x;           // 8 cols per thread
    if(c8 >= TRGV/8) return;                         // 3750
    int row = blockIdx.y;                            // 0..5119
    int c0 = c8*8;
    float* op = out + (size_t)row*TRGV + c0;
    if(row < NB){
        float4 A = make_float4(-1.f,-1.f,-1.f,-1.f);
        float4 B4 = A;
        if(c0 == 0) A.z = 0.f;                       // col 2
        *(float4*)op = A;
        *(float4*)(op+4) = B4;
    } else {
        int m = row - NB;
        float l = __ldg(&g_lse[m]);
        uint4 pk = *(const uint4*)(g_logit + (size_t)m*NPV + c0);
        __nv_bfloat162 h0 = *reinterpret_cast<__nv_bfloat162*>(&pk.x);
        __nv_bfloat162 h1 = *reinterpret_cast<__nv_bfloat162*>(&pk.y);
        __nv_bfloat162 h2 = *reinterpret_cast<__nv_bfloat162*>(&pk.z);
        __nv_bfloat162 h3 = *reinterpret_cast<__nv_bfloat162*>(&pk.w);
        float2 f0 = __bfloat1622float2(h0);
        float2 f1 = __bfloat1622float2(h1);
        float2 f2 = __bfloat1622float2(h2);
        float2 f3 = __bfloat1622float2(h3);
        float4 A  = make_float4(f0.x - l, f0.y - l, f1.x - l, f1.y - l);
        float4 B4 = make_float4(f2.x - l, f2.y - l, f3.x - l, f3.y - l);
        *(float4*)op = A;
        *(float4*)(op+4) = B4;
    }
}

// ----------------------------- launcher --------------------------------------
extern "C" void kernel_launch(void* const* d_in, const int* in_sizes, int n_in,
                              void* d_out, int out_size)
{
    const int*   src  = (const int*)  d_in[0];
    const int*   trg  = (const int*)  d_in[1];
    const float* EEMB = (const float*)d_in[3];
    const float* DEMB = (const float*)d_in[4];
    const float* ewf  = (const float*)d_in[5];
    const float* ewhf = (const float*)d_in[6];
    const float* ebf  = (const float*)d_in[7];
    const float* ewb  = (const float*)d_in[8];
    const float* ewhb = (const float*)d_in[9];
    const float* ebb  = (const float*)d_in[10];
    const float* Wi   = (const float*)d_in[11];
    const float* Wo   = (const float*)d_in[12];
    const float* dwih = (const float*)d_in[13];
    const float* dwhh = (const float*)d_in[14];
    const float* db   = (const float*)d_in[15];
    const float* genW = (const float*)d_in[16];
    const float* genb = (const float*)d_in[17];
    float* out = (float*)d_out;

    const int GEN_SMEM = 128*GP*2*2;                 // 69632 B

    cudaFuncSetAttribute(k_enc, cudaFuncAttributeMaxDynamicSharedMemorySize, 68608);
    cudaFuncSetAttribute(k_dec, cudaFuncAttributeMaxDynamicSharedMemorySize, 227328);
    cudaFuncSetAttribute(k_gen, cudaFuncAttributeMaxDynamicSharedMemorySize, GEN_SMEM);

    k_pack<<<416 + 15040, 256>>>(ewhf, ewhb, Wi, Wo, dwih, dwhh, genW, genb);
    k_pemb<<<800 + 624, 256>>>(src, trg, EEMB, DEMB, ewf, ebf, ewb, ebb, dwih, db);
    k_enc<<<NB, 256, 68608>>>();
    k_dec<<<NB, 256, 227328>>>();
    k_gen<<<dim3(NCB, DST), 256, GEN_SMEM>>>();
    k_lse<<<(GROWS+255)/256, 256>>>();
    k_fixrow<<<dim3(15, 5120), 256>>>(out);
}

// round 15
// speedup vs baseline: 1.4103x; 1.4103x over previous
#include <cuda_runtime.h>
#include <cuda_bf16.h>
#include <cuda_fp16.h>
#include <cuda_fp8.h>
#include <math.h>
#include <stdint.h>

#define SRCL  50
#define NB    128
#define TRGV  30000
#define NPV   30080
#define NCB   235
#define DST   39
#define GROWS 4992

// ----------------------------- device scratch -------------------------------
__device__ __align__(16) float          g_xin[2*SRCL*NB*256];
__device__ __align__(16) float          g_encout[SRCL*NB*128];
__device__ __align__(16) float          g_h0[NB*128];
__device__ __align__(16) float          g_c0[NB*128];
__device__ __align__(16) float          g_dpre[DST*NB*512];
__device__ __align__(16) __nv_bfloat16  g_hall[GROWS*128];
__device__ __align__(16) __nv_bfloat16  g_genW[NPV*128];
__device__ __align__(16) float          g_genb[NPV];
__device__ __align__(16) unsigned       g_ewhh[2*32*256];  // enc_w_hh packed [dir][k2][j]
__device__ __align__(16) unsigned       g_wiF8[32*128];    // attn_Wi  fp8 [k4][d]
__device__ __align__(16) unsigned       g_woF8[64*128];    // attn_Wo  fp8 [k4][j]
__device__ __align__(16) unsigned       g_whhF8[32*512];   // dec_w_hh fp8 [k4][j]
__device__ __align__(16) unsigned       g_wiaF8[32*512];   // dec_w_ih[:, :128] fp8 [k4][j]
__device__ __align__(16) float          g_part[NCB*GROWS];
__device__ __align__(16) float          g_lse[GROWS];
__device__ __align__(16) __nv_bfloat16  g_logit[(size_t)GROWS*NPV];   // 300 MB bf16 logits

// ----------------------------- helpers --------------------------------------
__device__ __forceinline__ unsigned pk2(float a, float b){
    __nv_bfloat162 h = __floats2bfloat162_rn(a, b);
    return *reinterpret_cast<unsigned*>(&h);
}
__device__ __forceinline__ float2 up2(unsigned u){
    __nv_bfloat162 h = *reinterpret_cast<__nv_bfloat162*>(&u);
    return __bfloat1622float2(h);
}
__device__ __forceinline__ unsigned pk4f8(float w0, float w1, float w2, float w3){
    __nv_fp8x2_storage_t lo = __nv_cvt_float2_to_fp8x2(make_float2(w0,w1), __NV_SATFINITE, __NV_E4M3);
    __nv_fp8x2_storage_t hi = __nv_cvt_float2_to_fp8x2(make_float2(w2,w3), __NV_SATFINITE, __NV_E4M3);
    return (unsigned)lo | ((unsigned)hi << 16);
}
__device__ __forceinline__ float4 up4f8(unsigned u){
    __half2_raw h0 = __nv_cvt_fp8x2_to_halfraw2((__nv_fp8x2_storage_t)(u & 0xffffu), __NV_E4M3);
    __half2_raw h1 = __nv_cvt_fp8x2_to_halfraw2((__nv_fp8x2_storage_t)(u >> 16), __NV_E4M3);
    float2 f0 = __half22float2(*reinterpret_cast<__half2*>(&h0));
    float2 f1 = __half22float2(*reinterpret_cast<__half2*>(&h1));
    return make_float4(f0.x, f0.y, f1.x, f1.y);
}
__device__ __forceinline__ float sigf(float x){
    return __fdividef(1.f, 1.f + __expf(-x));
}
__device__ __forceinline__ float tanh_(float x){
    float xc = fminf(15.f, fmaxf(-15.f, x));
    float e  = __expf(2.f*xc);
    return __fdividef(e - 1.f, e + 1.f);
}
__device__ __forceinline__ void mma16816(float* d, const unsigned* a, const unsigned* b){
    asm volatile("mma.sync.aligned.m16n8k16.row.col.f32.bf16.bf16.f32 "
        "{%0,%1,%2,%3}, {%4,%5,%6,%7}, {%8,%9}, {%0,%1,%2,%3};"
        : "+f"(d[0]), "+f"(d[1]), "+f"(d[2]), "+f"(d[3])
        : "r"(a[0]), "r"(a[1]), "r"(a[2]), "r"(a[3]), "r"(b[0]), "r"(b[1]));
}
__device__ __forceinline__ void ldsm4(unsigned* r, uint32_t addr){
    asm volatile("ldmatrix.sync.aligned.m8n8.x4.shared.b16 {%0,%1,%2,%3}, [%4];"
        : "=r"(r[0]), "=r"(r[1]), "=r"(r[2]), "=r"(r[3]) : "r"(addr));
}
__device__ __forceinline__ uint32_t s2u(const void* p){
    uint32_t a;
    asm("{ .reg .u64 t; cvta.to.shared.u64 t, %1; cvt.u32.u64 %0, t; }" : "=r"(a) : "l"(p));
    return a;
}

// ---------------- prep A: weight packing ------------------------------------
// blocks [0,240): fp8/bf16 small packs (61440 items) | [240, 240+15040): gen
__global__ void __launch_bounds__(256) k_pack(
    const float* __restrict__ ewhf, const float* __restrict__ ewhb,
    const float* __restrict__ Wi,   const float* __restrict__ Wo,
    const float* __restrict__ dwih, const float* __restrict__ dwhh,
    const float* __restrict__ genW, const float* __restrict__ genb)
{
    int blk = blockIdx.x, tid = threadIdx.x;
    if(blk < 240){
        int idx = blk*256 + tid;
        if(idx < 4096){ int q=idx>>7, d=idx&127; const float* p = Wi + d*128 + 4*q;
            g_wiF8[idx] = pk4f8(p[0], p[1], p[2], p[3]); return; }
        idx -= 4096;
        if(idx < 8192){ int q=idx>>7, j=idx&127; const float* p = Wo + j*256 + 4*q;
            g_woF8[idx] = pk4f8(p[0], p[1], p[2], p[3]); return; }
        idx -= 8192;
        if(idx < 16384){ int q=idx>>9, j=idx&511; const float* p = dwhh + j*128 + 4*q;
            g_whhF8[idx] = pk4f8(p[0], p[1], p[2], p[3]); return; }
        idx -= 16384;
        if(idx < 16384){ int q=idx>>9, j=idx&511; const float* p = dwih + j*158 + 4*q;
            g_wiaF8[idx] = pk4f8(p[0], p[1], p[2], p[3]); return; }
        idx -= 16384;
        { int dir=idx>>13, r=idx&8191, k2=r>>8, j=r&255;
          const float* wp = dir ? ewhb : ewhf;
          g_ewhh[dir*8192 + k2*256 + j] = pk2(wp[j*64+2*k2], wp[j*64+2*k2+1]); }
        return;
    }
    blk -= 240;
    {                                                // ---- pack generator
        int idx = blk*256 + tid;                     // < NPV*128
        int n = idx>>7, k = idx&127;
        g_genW[idx] = __float2bfloat16(n < TRGV ? genW[n*128+k] : 0.f);
        if(idx < NPV) g_genb[idx] = (idx < TRGV) ? genb[idx] : -1e30f;
        return;
    }
}

// ---------------- prep B: embedding pre-gates --------------------------------
__global__ void __launch_bounds__(256) k_pemb(
    const int* __restrict__ src, const int* __restrict__ trg,
    const float* __restrict__ EEMB, const float* __restrict__ DEMB,
    const float* __restrict__ ewf,  const float* __restrict__ ebf,
    const float* __restrict__ ewb,  const float* __restrict__ ebb,
    const float* __restrict__ dwih, const float* __restrict__ db)
{
    __shared__ float emb[16][32];
    int blk = blockIdx.x, tid = threadIdx.x;
    if(blk < 800){                                   // ---- encoder input gates
        int bi = blk>>3, b0 = (blk&7)*16;
        int dir = bi / SRCL, s = bi % SRCL;
        int j = tid;
        const float* w = dir ? ewb : ewf;
        float wr[30];
        #pragma unroll
        for(int e=0;e<30;e++) wr[e] = w[j*30+e];
        float bj = (dir ? ebb : ebf)[j];
        for(int i=tid;i<480;i+=256){
            int q=i/30, e=i%30; int tok = src[s*NB + b0 + q];
            emb[q][e] = EEMB[tok*30+e];
        }
        __syncthreads();
        #pragma unroll 4
        for(int q=0;q<16;q++){
            float a = bj;
            #pragma unroll
            for(int e=0;e<30;e++) a += wr[e]*emb[q][e];
            g_xin[((dir*SRCL+s)*NB + b0 + q)*256 + j] = a;
        }
        return;
    }
    blk -= 800;
    {                                                // ---- decoder pre-gates
        int t = blk>>4, sub = blk&15;
        int b0 = (sub>>1)*16;
        int j  = (sub&1)*256 + tid;
        float wr[30];
        #pragma unroll
        for(int e=0;e<30;e++) wr[e] = dwih[j*158 + 128 + e];
        float bj = db[j];
        for(int i=tid;i<480;i+=256){
            int q=i/30, e=i%30; int tok = trg[t*NB + b0 + q];
            emb[q][e] = DEMB[tok*30+e];
        }
        __syncthreads();
        #pragma unroll 4
        for(int q=0;q<16;q++){
            float a = bj;
            #pragma unroll
            for(int e=0;e<30;e++) a += wr[e]*emb[q][e];
            g_dpre[(t*NB + b0 + q)*512 + j] = a;
        }
        return;
    }
}

// ------------------------------- encoder recurrence --------------------------
__global__ void k_enc()
{
    extern __shared__ char sm[];
    unsigned* ws = (unsigned*)sm;                       // 16384 u (64KB)
    float* hs = (float*)(sm + 65536);                   // 128
    float* cs = hs + 128;                               // 128
    float* gb = cs + 128;                               // 512
    int b = blockIdx.x, tid = threadIdx.x;

    { uint4* d4=(uint4*)ws; const uint4* s4=(const uint4*)g_ewhh;
      for(int i=tid;i<4096;i+=256) d4[i]=s4[i]; }
    if(tid < 128){ hs[tid]=0.f; cs[tid]=0.f; }
    __syncthreads();

    for(int t=0;t<SRCL;t++){
        float af = g_xin[((0*SRCL + t        )*NB+b)*256 + tid];
        float ab = g_xin[((1*SRCL + (SRCL-1-t))*NB+b)*256 + tid];
        #pragma unroll 8
        for(int k2=0;k2<32;k2++){
            float h0 = hs[2*k2], h1 = hs[2*k2+1];
            float2 wf2 = up2(ws[k2*256 + tid]);
            af += h0*wf2.x + h1*wf2.y;
            float g0 = hs[64+2*k2], g1 = hs[64+2*k2+1];
            float2 wb2 = up2(ws[8192 + k2*256 + tid]);
            ab += g0*wb2.x + g1*wb2.y;
        }
        gb[tid] = af; gb[256+tid] = ab;
        __syncthreads();
        if(tid < 128){
            int dir = tid>>6, d = tid&63;
            float* g = gb + dir*256;
            float iv=g[d], fv=g[64+d], gv=g[128+d], ov=g[192+d];
            float cn = sigf(fv)*cs[dir*64+d] + sigf(iv)*tanh_(gv);
            float hn = sigf(ov)*tanh_(cn);
            cs[dir*64+d]=cn; hs[dir*64+d]=hn;
            int s_out = dir ? (SRCL-1-t) : t;
            g_encout[(s_out*NB+b)*128 + dir*64 + d] = hn;
        }
        __syncthreads();
    }
    if(tid < 64){
        g_h0[b*128+2*tid]   = hs[tid];
        g_h0[b*128+2*tid+1] = hs[64+tid];
        g_c0[b*128+2*tid]   = cs[tid];
        g_c0[b*128+2*tid+1] = cs[64+tid];
    }
}

// ------------------------------- decoder recurrence --------------------------
// ALL weights fp8-E4M3 in smem (206KB total) -> zero L2-latency loads in loop.
// smem: wis 16KB @0 | wos 32KB @16384 | whh 64KB @49152 | wia 64KB @114688
//       encs 25.6KB @180224 | state @205824 .. 210944
__global__ void __launch_bounds__(256) k_dec()
{
    extern __shared__ char sm[];
    unsigned* wis  = (unsigned*)(sm);
    unsigned* wos  = (unsigned*)(sm + 16384);
    unsigned* whh  = (unsigned*)(sm + 49152);
    unsigned* wia  = (unsigned*)(sm + 114688);
    float*    encs = (float*)   (sm + 180224);
    float*    h    = (float*)   (sm + 205824);
    float*    c    = h    + 128;
    float*    semi = c    + 128;
    float*    st   = semi + 128;
    float*    ct   = st   + 128;
    float*    es   = ct   + 128;                    // 64
    float*    sc   = es   + 64;                     // 64
    float*    gb   = sc   + 64;                     // 512
    int b = blockIdx.x, tid = threadIdx.x;
    int lane = tid & 31, w = tid >> 5;

    { uint4* d4=(uint4*)wis; const uint4* s4=(const uint4*)g_wiF8;
      for(int i=tid;i<1024;i+=256) d4[i]=s4[i]; }
    { uint4* d4=(uint4*)wos; const uint4* s4=(const uint4*)g_woF8;
      for(int i=tid;i<2048;i+=256) d4[i]=s4[i]; }
    { uint4* d4=(uint4*)whh; const uint4* s4=(const uint4*)g_whhF8;
      for(int i=tid;i<4096;i+=256) d4[i]=s4[i]; }
    { uint4* d4=(uint4*)wia; const uint4* s4=(const uint4*)g_wiaF8;
      for(int i=tid;i<4096;i+=256) d4[i]=s4[i]; }
    { float4* d4=(float4*)encs; const float4* s4=(const float4*)g_encout;
      for(int i=tid;i<1600;i+=256){ int s=i>>5, r=i&31; d4[i]=s4[(s*NB+b)*32 + r]; } }
    if(tid < 128){ h[tid]=g_h0[b*128+tid]; c[tid]=g_c0[b*128+tid]; }
    __syncthreads();

    for(int t=0;t<DST;t++){
        // prefetch pre-gates (independent of all phases; hides L2 latency)
        const float* pre = g_dpre + (t*NB+b)*512;
        float p0 = __ldg(&pre[tid]);
        float p1 = __ldg(&pre[tid+256]);

        // 1) semi = h @ Wi.T   (fp8 smem weights, 2 accumulators)
        if(tid < 128){
            float a0 = 0.f, a1 = 0.f;
            #pragma unroll
            for(int q=0;q<32;q+=2){
                float4 x0 = *(const float4*)(h + 4*q);
                float4 w0 = up4f8(wis[q*128 + tid]);
                a0 += x0.x*w0.x + x0.y*w0.y + x0.z*w0.z + x0.w*w0.w;
                float4 x1 = *(const float4*)(h + 4*q + 4);
                float4 w1 = up4f8(wis[(q+1)*128 + tid]);
                a1 += x1.x*w1.x + x1.y*w1.y + x1.z*w1.z + x1.w*w1.w;
            }
            semi[tid] = a0 + a1;
        }
        __syncthreads();
        // 2) attention scores
        for(int s=w; s<SRCL; s+=8){
            const float* er = encs + s*128;
            float a = er[lane]*semi[lane] + er[lane+32]*semi[lane+32]
                    + er[lane+64]*semi[lane+64] + er[lane+96]*semi[lane+96];
            #pragma unroll
            for(int o=16;o>0;o>>=1) a += __shfl_xor_sync(0xffffffffu, a, o);
            if(lane==0) es[s] = a;
        }
        __syncthreads();
        // 3) softmax over 50 (warp 0)
        if(w == 0){
            float v0 = (lane    < SRCL) ? es[lane]    : -1e30f;
            float v1 = (lane+32 < SRCL) ? es[lane+32] : -1e30f;
            float m = fmaxf(v0, v1);
            #pragma unroll
            for(int o=16;o>0;o>>=1) m = fmaxf(m, __shfl_xor_sync(0xffffffffu, m, o));
            float e0 = (lane    < SRCL) ? __expf(v0-m) : 0.f;
            float e1 = (lane+32 < SRCL) ? __expf(v1-m) : 0.f;
            float ssum = e0 + e1;
            #pragma unroll
            for(int o=16;o>0;o>>=1) ssum += __shfl_xor_sync(0xffffffffu, ssum, o);
            float inv = __fdividef(1.f, ssum);
            if(lane    < SRCL) sc[lane]    = e0*inv;
            if(lane+32 < SRCL) sc[lane+32] = e1*inv;
        }
        __syncthreads();
        // 4) s_tilde
        if(tid < 128){
            float a0 = 0.f, a1 = 0.f;
            #pragma unroll
            for(int s=0;s<SRCL;s+=2){
                a0 += sc[s]*encs[s*128 + tid];
                a1 += sc[s+1]*encs[(s+1)*128 + tid];
            }
            st[tid] = a0 + a1;
        }
        __syncthreads();
        // 5) c_t = tanh([s_tilde,h] @ Wo.T)
        if(tid < 128){
            float a0 = 0.f, a1 = 0.f;
            #pragma unroll
            for(int q=0;q<32;q+=2){
                float4 x0 = *(const float4*)(st + 4*q);
                float4 w0 = up4f8(wos[q*128 + tid]);
                a0 += x0.x*w0.x + x0.y*w0.y + x0.z*w0.z + x0.w*w0.w;
                float4 x1 = *(const float4*)(st + 4*q + 4);
                float4 w1 = up4f8(wos[(q+1)*128 + tid]);
                a1 += x1.x*w1.x + x1.y*w1.y + x1.z*w1.z + x1.w*w1.w;
            }
            #pragma unroll
            for(int q=0;q<32;q+=2){
                float4 x0 = *(const float4*)(h + 4*q);
                float4 w0 = up4f8(wos[(32+q)*128 + tid]);
                a0 += x0.x*w0.x + x0.y*w0.y + x0.z*w0.z + x0.w*w0.w;
                float4 x1 = *(const float4*)(h + 4*q + 4);
                float4 w1 = up4f8(wos[(33+q)*128 + tid]);
                a1 += x1.x*w1.x + x1.y*w1.y + x1.z*w1.z + x1.w*w1.w;
            }
            ct[tid] = tanh_(a0 + a1);
        }
        __syncthreads();
        // 6) gates = pre + c_t@w_ihA.T + h@w_hh.T  (2 gates/thread, 4 accs)
        {
            float a0 = p0, a1 = p1, b0 = 0.f, b1 = 0.f;
            #pragma unroll
            for(int q=0;q<32;q+=2){
                float4 x = *(const float4*)(ct + 4*q);
                float4 v0 = up4f8(wia[q*512 + tid]);
                float4 v1 = up4f8(wia[q*512 + tid + 256]);
                a0 += x.x*v0.x + x.y*v0.y + x.z*v0.z + x.w*v0.w;
                a1 += x.x*v1.x + x.y*v1.y + x.z*v1.z + x.w*v1.w;
                float4 x2 = *(const float4*)(ct + 4*q + 4);
                float4 v2 = up4f8(wia[(q+1)*512 + tid]);
                float4 v3 = up4f8(wia[(q+1)*512 + tid + 256]);
                b0 += x2.x*v2.x + x2.y*v2.y + x2.z*v2.z + x2.w*v2.w;
                b1 += x2.x*v3.x + x2.y*v3.y + x2.z*v3.z + x2.w*v3.w;
            }
            #pragma unroll
            for(int q=0;q<32;q+=2){
                float4 y = *(const float4*)(h + 4*q);
                float4 v0 = up4f8(whh[q*512 + tid]);
                float4 v1 = up4f8(whh[q*512 + tid + 256]);
                a0 += y.x*v0.x + y.y*v0.y + y.z*v0.z + y.w*v0.w;
                a1 += y.x*v1.x + y.y*v1.y + y.z*v1.z + y.w*v1.w;
                float4 y2 = *(const float4*)(h + 4*q + 4);
                float4 v2 = up4f8(whh[(q+1)*512 + tid]);
                float4 v3 = up4f8(whh[(q+1)*512 + tid + 256]);
                b0 += y2.x*v2.x + y2.y*v2.y + y2.z*v2.z + y2.w*v2.w;
                b1 += y2.x*v3.x + y2.y*v3.y + y2.z*v3.z + y2.w*v3.w;
            }
            gb[tid] = a0 + b0; gb[tid+256] = a1 + b1;
        }
        __syncthreads();
        // 7) LSTM update
        if(tid < 128){
            float iv=gb[tid], fv=gb[128+tid], gv=gb[256+tid], ov=gb[384+tid];
            float cn = sigf(fv)*c[tid] + sigf(iv)*tanh_(gv);
            float hn = sigf(ov)*tanh_(cn);
            c[tid]=cn; h[tid]=hn;
            g_hall[(t*NB+b)*128 + tid] = __float2bfloat16(hn);
        }
        __syncthreads();
    }
}

// ------------------- generator GEMM (mma.sync + ldmatrix) --------------------
#define GP 136
#define CP 132
__global__ void __launch_bounds__(256) k_gen()
{
    extern __shared__ char sm[];
    __nv_bfloat16* As = (__nv_bfloat16*)sm;
    __nv_bfloat16* Bs = As + 128*GP;
    int tid = threadIdx.x, w = tid>>5, lane = tid&31;
    int mb = blockIdx.y, nb = blockIdx.x;

    const uint4* Asrc = (const uint4*)(g_hall + (size_t)mb*128*128);
    const uint4* Bsrc = (const uint4*)(g_genW + (size_t)nb*128*128);
    for(int i=tid;i<2048;i+=256){
        int r=i>>4, c=i&15;
        *(uint4*)(As + r*GP + c*8) = Asrc[i];
    }
    for(int i=tid;i<2048;i+=256){
        int r=i>>4, c=i&15;
        *(uint4*)(Bs + r*GP + c*8) = Bsrc[i];
    }
    __syncthreads();

    int wm = w & 3, wn = w >> 2;                    // warp grid 4x2
    int m0 = wm*32, n0 = wn*64;

    float acc[2][8][4];
    #pragma unroll
    for(int mi=0;mi<2;mi++)
        #pragma unroll
        for(int ni=0;ni<8;ni++)
            #pragma unroll
            for(int q=0;q<4;q++) acc[mi][ni][q] = 0.f;

    uint32_t As_u = s2u(As), Bs_u = s2u(Bs);
    uint32_t aAddr = As_u + (uint32_t)((m0 + (lane & 15))*GP + (lane >> 4)*8)*2;
    uint32_t bAddr = Bs_u + (uint32_t)((n0 + ((lane >> 4) & 1)*8 + (lane & 7))*GP
                                       + ((lane >> 3) & 1)*8)*2;

    #pragma unroll
    for(int ks=0;ks<8;ks++){
        uint32_t kOff = ks*32;
        unsigned a[2][4];
        ldsm4(a[0], aAddr + kOff);
        ldsm4(a[1], aAddr + 16*GP*2 + kOff);
        #pragma unroll
        for(int nip=0;nip<4;nip++){
            unsigned bq[4];
            ldsm4(bq, bAddr + (uint32_t)(nip*16*GP)*2 + kOff);
            mma16816(acc[0][nip*2+0], a[0], bq+0);
            mma16816(acc[1][nip*2+0], a[1], bq+0);
            mma16816(acc[0][nip*2+1], a[0], bq+2);
            mma16816(acc[1][nip*2+1], a[1], bq+2);
        }
    }
    __syncthreads();

    int lq = lane>>2, lr = lane&3;
    float* Cs = (float*)sm;
    #pragma unroll
    for(int mi=0;mi<2;mi++){
        #pragma unroll
        for(int ni=0;ni<8;ni++){
            float* cr = Cs + (m0+mi*16+lq)*CP + n0 + ni*8 + 2*lr;
            cr[0] = acc[mi][ni][0]; cr[1] = acc[mi][ni][1];
            cr[8*CP] = acc[mi][ni][2]; cr[8*CP+1] = acc[mi][ni][3];
        }
    }
    __syncthreads();

    float4 bias = *(const float4*)(g_genb + nb*128 + lane*4);
    __nv_bfloat16* lbase = g_logit + (size_t)(mb*128)*NPV + nb*128 + lane*4;
    #pragma unroll 4
    for(int rr=0; rr<16; rr++){
        int r = w*16 + rr;
        const float* row = Cs + r*CP + lane*4;
        float v0 = row[0] + bias.x;
        float v1 = row[1] + bias.y;
        float v2 = row[2] + bias.z;
        float v3 = row[3] + bias.w;
        float s = __expf(v0) + __expf(v1) + __expf(v2) + __expf(v3);
        #pragma unroll
        for(int o=16;o>0;o>>=1) s += __shfl_xor_sync(0xffffffffu, s, o);
        if(lane == 0) g_part[nb*GROWS + mb*128 + r] = s;
        __nv_bfloat162 q0 = __floats2bfloat162_rn(v0, v1);
        __nv_bfloat162 q1 = __floats2bfloat162_rn(v2, v3);
        uint2 pk;
        pk.x = *reinterpret_cast<unsigned*>(&q0);
        pk.y = *reinterpret_cast<unsigned*>(&q1);
        *(uint2*)(lbase + (size_t)r*NPV) = pk;
    }
}

__global__ void k_lse()
{
    int m = blockIdx.x*256 + threadIdx.x;
    if(m >= GROWS) return;
    float s = 0.f;
    for(int nb=0;nb<NCB;nb++) s += g_part[nb*GROWS + m];
    g_lse[m] = logf(s);
}

// rows < NB: constant row0; rows >= NB: out = bf16logit - lse (streaming)
__global__ void __launch_bounds__(256) k_fixrow(float* __restrict__ out)
{
    int c8 = blockIdx.x*256 + threadIdx.x;           // 8 cols per thread
    if(c8 >= TRGV/8) return;                         // 3750
    int row = blockIdx.y;                            // 0..5119
    int c0 = c8*8;
    float* op = out + (size_t)row*TRGV + c0;
    if(row < NB){
        float4 A = make_float4(-1.f,-1.f,-1.f,-1.f);
        float4 B4 = A;
        if(c0 == 0) A.z = 0.f;                       // col 2
        *(float4*)op = A;
        *(float4*)(op+4) = B4;
    } else {
        int m = row - NB;
        float l = __ldg(&g_lse[m]);
        uint4 pk = *(const uint4*)(g_logit + (size_t)m*NPV + c0);
        __nv_bfloat162 h0 = *reinterpret_cast<__nv_bfloat162*>(&pk.x);
        __nv_bfloat162 h1 = *reinterpret_cast<__nv_bfloat162*>(&pk.y);
        __nv_bfloat162 h2 = *reinterpret_cast<__nv_bfloat162*>(&pk.z);
        __nv_bfloat162 h3 = *reinterpret_cast<__nv_bfloat162*>(&pk.w);
        float2 f0 = __bfloat1622float2(h0);
        float2 f1 = __bfloat1622float2(h1);
        float2 f2 = __bfloat1622float2(h2);
        float2 f3 = __bfloat1622float2(h3);
        float4 A  = make_float4(f0.x - l, f0.y - l, f1.x - l, f1.y - l);
        float4 B4 = make_float4(f2.x - l, f2.y - l, f3.x - l, f3.y - l);
        *(float4*)op = A;
        *(float4*)(op+4) = B4;
    }
}

// ----------------------------- launcher --------------------------------------
extern "C" void kernel_launch(void* const* d_in, const int* in_sizes, int n_in,
                              void* d_out, int out_size)
{
    const int*   src  = (const int*)  d_in[0];
    const int*   trg  = (const int*)  d_in[1];
    const float* EEMB = (const float*)d_in[3];
    const float* DEMB = (const float*)d_in[4];
    const float* ewf  = (const float*)d_in[5];
    const float* ewhf = (const float*)d_in[6];
    const float* ebf  = (const float*)d_in[7];
    const float* ewb  = (const float*)d_in[8];
    const float* ewhb = (const float*)d_in[9];
    const float* ebb  = (const float*)d_in[10];
    const float* Wi   = (const float*)d_in[11];
    const float* Wo   = (const float*)d_in[12];
    const float* dwih = (const float*)d_in[13];
    const float* dwhh = (const float*)d_in[14];
    const float* db   = (const float*)d_in[15];
    const float* genW = (const float*)d_in[16];
    const float* genb = (const float*)d_in[17];
    float* out = (float*)d_out;

    const int GEN_SMEM = 128*GP*2*2;                 // 69632 B
    const int DEC_SMEM = 210944;                     // fp8 weights + encs + state

    cudaFuncSetAttribute(k_enc, cudaFuncAttributeMaxDynamicSharedMemorySize, 68608);
    cudaFuncSetAttribute(k_dec, cudaFuncAttributeMaxDynamicSharedMemorySize, DEC_SMEM);
    cudaFuncSetAttribute(k_gen, cudaFuncAttributeMaxDynamicSharedMemorySize, GEN_SMEM);

    k_pack<<<240 + 15040, 256>>>(ewhf, ewhb, Wi, Wo, dwih, dwhh, genW, genb);
    k_pemb<<<800 + 624, 256>>>(src, trg, EEMB, DEMB, ewf, ebf, ewb, ebb, dwih, db);
    k_enc<<<NB, 256, 68608>>>();
    k_dec<<<NB, 256, DEC_SMEM>>>();
    k_gen<<<dim3(NCB, DST), 256, GEN_SMEM>>>();
    k_lse<<<(GROWS+255)/256, 256>>>();
    k_fixrow<<<dim3(15, 5120), 256>>>(out);
}